// round 5
// baseline (speedup 1.0000x reference)
#include <cuda_runtime.h>

#define NN   4096
#define HH   128
#define CAP  192   // max degree capacity; Binomial(4096,0.02) max ~= 127

// Scratch (device globals: allocation-free per harness rules)
__device__ float4 g_edge[NN * CAP];   // (j_bits, decay, wc, pad) per edge
__device__ int    g_deg[NN];
__device__ float  g_h[NN * HH];
__device__ float  g_m[NN * HH];
__device__ float  g_W1t[HH * 256];    // W1 transposed: [c][k], k=0..255
__device__ float  g_W2t[HH * HH];     // W2 transposed: [c][k], k=0..127

// ---- packed fp32x2 helpers (Blackwell FFMA2) ----
__device__ __forceinline__ unsigned long long fma2(
    unsigned long long a, unsigned long long b, unsigned long long c)
{
    unsigned long long d;
    asm("fma.rn.f32x2 %0, %1, %2, %3;" : "=l"(d) : "l"(a), "l"(b), "l"(c));
    return d;
}
__device__ __forceinline__ float f32x2_sum(unsigned long long v)
{
    float lo, hi;
    asm("mov.b64 {%0, %1}, %2;" : "=f"(lo), "=f"(hi) : "l"(v));
    return lo + hi;
}

// ---------------------------------------------------------------------------
// Tiled transpose: dst[C][R] = src[R][C]
// ---------------------------------------------------------------------------
__global__ void transpose_kernel(const float* __restrict__ src,
                                 float* __restrict__ dst, int R, int C)
{
    __shared__ float tile[32][33];
    int bx = blockIdx.x * 32, by = blockIdx.y * 32;
    int x = bx + threadIdx.x;
#pragma unroll
    for (int dy = 0; dy < 32; dy += 8) {
        int y = by + threadIdx.y + dy;
        if (y < R && x < C) tile[threadIdx.y + dy][threadIdx.x] = src[y * C + x];
    }
    __syncthreads();
    x = by + threadIdx.x;
#pragma unroll
    for (int dy = 0; dy < 32; dy += 8) {
        int y = bx + threadIdx.y + dy;
        if (y < C && x < R) dst[y * R + x] = tile[threadIdx.x][threadIdx.y + dy];
    }
}

// ---------------------------------------------------------------------------
// Build per-row edge list from adj (2% dense) with loop-invariant weights.
// One warp per row; float4 adj scan (512B per warp-load, MLP=2 lines of 128B).
// Edge order within a row is a fixed permutation (sum order is irrelevant).
// ---------------------------------------------------------------------------
__global__ __launch_bounds__(256) void build_edges_kernel(
    const float* __restrict__ adj, const float* __restrict__ dist)
{
    int row  = blockIdx.x * 8 + (threadIdx.x >> 5);
    int lane = threadIdx.x & 31;
    if (row >= NN) return;
    const float4* arowv = (const float4*)(adj + (long)row * NN);  // 1024 float4
    const float*  drow  = dist + (long)row * NN;
    unsigned lt = (1u << lane) - 1u;
    int base = 0;
    for (int it = 0; it < 1024; it += 64) {
        float4 a = arowv[it + lane];
        float4 b = arowv[it + 32 + lane];
        unsigned m0 = __ballot_sync(0xffffffffu, a.x != 0.0f);
        unsigned m1 = __ballot_sync(0xffffffffu, a.y != 0.0f);
        unsigned m2 = __ballot_sync(0xffffffffu, a.z != 0.0f);
        unsigned m3 = __ballot_sync(0xffffffffu, a.w != 0.0f);
        unsigned n0 = __ballot_sync(0xffffffffu, b.x != 0.0f);
        unsigned n1 = __ballot_sync(0xffffffffu, b.y != 0.0f);
        unsigned n2 = __ballot_sync(0xffffffffu, b.z != 0.0f);
        unsigned n3 = __ballot_sync(0xffffffffu, b.w != 0.0f);
#pragma unroll
        for (int q = 0; q < 8; q++) {
            unsigned mask;
            float av;
            int col;
            switch (q) {
                case 0: mask = m0; av = a.x; col = (it + lane) * 4 + 0; break;
                case 1: mask = m1; av = a.y; col = (it + lane) * 4 + 1; break;
                case 2: mask = m2; av = a.z; col = (it + lane) * 4 + 2; break;
                case 3: mask = m3; av = a.w; col = (it + lane) * 4 + 3; break;
                case 4: mask = n0; av = b.x; col = (it + 32 + lane) * 4 + 0; break;
                case 5: mask = n1; av = b.y; col = (it + 32 + lane) * 4 + 1; break;
                case 6: mask = n2; av = b.z; col = (it + 32 + lane) * 4 + 2; break;
                default: mask = n3; av = b.w; col = (it + 32 + lane) * 4 + 3; break;
            }
            if (av != 0.0f) {
                int pos = base + __popc(mask & lt);
                if (pos < CAP) {
                    float d     = drow[col];
                    float decay = __expf(d * (-1.0f / 3.0f));
                    float r     = fmaxf(d, 1e-6f);
                    float inv   = 3.5f / r;
                    float i2    = inv * inv;
                    float i6    = i2 * i2 * i2;
                    float wc    = 0.04f * (i6 * i6 - i6);
                    g_edge[row * CAP + pos] =
                        make_float4(__int_as_float(col), decay, wc, 0.0f);
                }
            }
            base += __popc(mask);
        }
    }
    if (lane == 0) g_deg[row] = (base < CAP) ? base : CAP;
}

// ---------------------------------------------------------------------------
// h = x @ W_in + b_in      (4096x64 @ 64x128); 8 rows/block, grid 512
// ---------------------------------------------------------------------------
__global__ __launch_bounds__(128) void in_proj_kernel(
    const float* __restrict__ x, const float* __restrict__ W,
    const float* __restrict__ b)
{
    __shared__ float sx[8 * 64];
    int c  = threadIdx.x;
    int r0 = blockIdx.x * 8;
    for (int i = threadIdx.x; i < 8 * 64; i += 128)
        sx[i] = x[(long)r0 * 64 + i];
    __syncthreads();

    float acc[8];
#pragma unroll
    for (int r = 0; r < 8; r++) acc[r] = 0.0f;

#pragma unroll 4
    for (int k = 0; k < 64; k += 4) {
        float w0 = W[(k + 0) * HH + c];
        float w1 = W[(k + 1) * HH + c];
        float w2 = W[(k + 2) * HH + c];
        float w3 = W[(k + 3) * HH + c];
#pragma unroll
        for (int r = 0; r < 8; r++) {
            float4 xv = *(const float4*)&sx[r * 64 + k];
            acc[r] = fmaf(xv.x, w0, fmaf(xv.y, w1, fmaf(xv.z, w2, fmaf(xv.w, w3, acc[r]))));
        }
    }
    float bias = b[c];
#pragma unroll
    for (int r = 0; r < 8; r++)
        g_h[(long)(r0 + r) * HH + c] = acc[r] + bias;
}

// ---------------------------------------------------------------------------
// m_i = sum_{j in N(i)} (decay_ij * relu(<h_i, h_j>) + wc_ij) * h_j
// One block (4 warps) per row; warps take edge PAIRS (stride 8) so the two
// shfl-reduce chains interleave. Lane owns 4 hidden dims.   [R2 version]
// ---------------------------------------------------------------------------
__global__ __launch_bounds__(128) void msg_kernel()
{
    __shared__ float s_hi[HH];
    __shared__ float s_m[4 * HH];
    int row  = blockIdx.x;
    int tid  = threadIdx.x;
    int wid  = tid >> 5;
    int lane = tid & 31;

    s_hi[tid] = g_h[(long)row * HH + tid];
    __syncthreads();
    float4 hi4 = *(const float4*)&s_hi[lane * 4];

    int deg = g_deg[row];
    const float4* ebase = &g_edge[row * CAP];
    float4 acc = make_float4(0.f, 0.f, 0.f, 0.f);

    int e = wid * 2;
    for (; e + 1 < deg; e += 8) {
        float4 em0 = ebase[e];
        float4 em1 = ebase[e + 1];
        int j0 = __float_as_int(em0.x);
        int j1 = __float_as_int(em1.x);
        float4 hj0 = *(const float4*)&g_h[(long)j0 * HH + lane * 4];
        float4 hj1 = *(const float4*)&g_h[(long)j1 * HH + lane * 4];
        float d0 = hi4.x * hj0.x + hi4.y * hj0.y + hi4.z * hj0.z + hi4.w * hj0.w;
        float d1 = hi4.x * hj1.x + hi4.y * hj1.y + hi4.z * hj1.z + hi4.w * hj1.w;
#pragma unroll
        for (int o = 16; o > 0; o >>= 1) {
            d0 += __shfl_xor_sync(0xffffffffu, d0, o);
            d1 += __shfl_xor_sync(0xffffffffu, d1, o);
        }
        float c0 = fmaf(em0.y, fmaxf(d0, 0.0f), em0.z);
        float c1 = fmaf(em1.y, fmaxf(d1, 0.0f), em1.z);
        acc.x = fmaf(c1, hj1.x, fmaf(c0, hj0.x, acc.x));
        acc.y = fmaf(c1, hj1.y, fmaf(c0, hj0.y, acc.y));
        acc.z = fmaf(c1, hj1.z, fmaf(c0, hj0.z, acc.z));
        acc.w = fmaf(c1, hj1.w, fmaf(c0, hj0.w, acc.w));
    }
    if (e < deg) {   // odd tail edge owned by this warp
        float4 em = ebase[e];
        int j = __float_as_int(em.x);
        float4 hj = *(const float4*)&g_h[(long)j * HH + lane * 4];
        float dot = hi4.x * hj.x + hi4.y * hj.y + hi4.z * hj.z + hi4.w * hj.w;
#pragma unroll
        for (int o = 16; o > 0; o >>= 1)
            dot += __shfl_xor_sync(0xffffffffu, dot, o);
        float cf = fmaf(em.y, fmaxf(dot, 0.0f), em.z);
        acc.x = fmaf(cf, hj.x, acc.x);
        acc.y = fmaf(cf, hj.y, acc.y);
        acc.z = fmaf(cf, hj.z, acc.z);
        acc.w = fmaf(cf, hj.w, acc.w);
    }
    *(float4*)&s_m[wid * HH + lane * 4] = acc;
    __syncthreads();
    g_m[(long)row * HH + tid] =
        s_m[tid] + s_m[HH + tid] + s_m[2 * HH + tid] + s_m[3 * HH + tid];
}

// ---------------------------------------------------------------------------
// Fused update: t = relu([h|m]@W1+b1); delta = t@W2+b2; out = LN(h+delta)
// 4 rows/block -> grid 1024. Packed f32x2 FMA + transposed weights (LDG.128).
// ---------------------------------------------------------------------------
__global__ __launch_bounds__(128) void update_kernel(
    const float* __restrict__ b1, const float* __restrict__ b2,
    const float* __restrict__ gamma, const float* __restrict__ beta,
    float* __restrict__ out)
{
    __shared__ float s_cat[4 * 256];   // [r][0:128)=h, [r][128:256)=m, later y
    __shared__ float s_t[4 * 128];
    int c  = threadIdx.x;
    int r0 = blockIdx.x * 4;

    for (int i = threadIdx.x; i < 4 * 128; i += 128) {
        int r = i >> 7, k = i & 127;
        s_cat[r * 256 + k]       = g_h[(long)(r0 + r) * HH + k];
        s_cat[r * 256 + 128 + k] = g_m[(long)(r0 + r) * HH + k];
    }
    __syncthreads();

    typedef unsigned long long u64;
    // ---- mlp1: t = relu(cat @ W1 + b1), f32x2 packed over k ----
    u64 p0[4], p1[4];
#pragma unroll
    for (int r = 0; r < 4; r++) { p0[r] = 0ull; p1[r] = 0ull; }
    const float* w1p = &g_W1t[c * 256];
#pragma unroll 4
    for (int k = 0; k < 256; k += 4) {
        ulonglong2 wv = *(const ulonglong2*)(w1p + k);
#pragma unroll
        for (int r = 0; r < 4; r++) {
            ulonglong2 cv = *(const ulonglong2*)&s_cat[r * 256 + k];
            p0[r] = fma2(cv.x, wv.x, p0[r]);
            p1[r] = fma2(cv.y, wv.y, p1[r]);
        }
    }
    {
        float bias = b1[c];
#pragma unroll
        for (int r = 0; r < 4; r++)
            s_t[r * 128 + c] = fmaxf(f32x2_sum(p0[r]) + f32x2_sum(p1[r]) + bias, 0.0f);
    }
    __syncthreads();

    // ---- mlp2: delta = t @ W2 + b2 ----
#pragma unroll
    for (int r = 0; r < 4; r++) { p0[r] = 0ull; p1[r] = 0ull; }
    const float* w2p = &g_W2t[c * 128];
#pragma unroll 4
    for (int k = 0; k < 128; k += 4) {
        ulonglong2 wv = *(const ulonglong2*)(w2p + k);
#pragma unroll
        for (int r = 0; r < 4; r++) {
            ulonglong2 tv = *(const ulonglong2*)&s_t[r * 128 + k];
            p0[r] = fma2(tv.x, wv.x, p0[r]);
            p1[r] = fma2(tv.y, wv.y, p1[r]);
        }
    }
    // y = h + delta + b2 -> overwrite m-region (all m reads finished pre-sync)
    {
        float bias = b2[c];
#pragma unroll
        for (int r = 0; r < 4; r++)
            s_cat[r * 256 + 128 + c] =
                s_cat[r * 256 + c] + f32x2_sum(p0[r]) + f32x2_sum(p1[r]) + bias;
    }
    __syncthreads();

    // ---- layernorm: warp wid handles row wid; lane owns 4 cols ----
    int wid  = c >> 5;
    int lane = c & 31;
    float4 gm = *(const float4*)&gamma[lane * 4];
    float4 bt = *(const float4*)&beta[lane * 4];
    {
        int r = wid;
        float4 yv = *(const float4*)&s_cat[r * 256 + 128 + lane * 4];
        float s = yv.x + yv.y + yv.z + yv.w;
#pragma unroll
        for (int o = 16; o > 0; o >>= 1)
            s += __shfl_xor_sync(0xffffffffu, s, o);
        float mu = s * (1.0f / 128.0f);
        float dx = yv.x - mu, dy = yv.y - mu, dz = yv.z - mu, dw = yv.w - mu;
        float sq = dx * dx + dy * dy + dz * dz + dw * dw;
#pragma unroll
        for (int o = 16; o > 0; o >>= 1)
            sq += __shfl_xor_sync(0xffffffffu, sq, o);
        float rs = rsqrtf(sq * (1.0f / 128.0f) + 1e-5f);
        float4 o4;
        o4.x = dx * rs * gm.x + bt.x;
        o4.y = dy * rs * gm.y + bt.y;
        o4.z = dz * rs * gm.z + bt.z;
        o4.w = dw * rs * gm.w + bt.w;
        *(float4*)&out[(long)(r0 + r) * HH + lane * 4] = o4;
    }
}

// ---------------------------------------------------------------------------
extern "C" void kernel_launch(void* const* d_in, const int* in_sizes, int n_in,
                              void* d_out, int out_size)
{
    const float* x     = (const float*)d_in[0];
    const float* adj   = (const float*)d_in[1];
    const float* dist  = (const float*)d_in[2];
    const float* W_in  = (const float*)d_in[3];
    const float* b_in  = (const float*)d_in[4];
    // d_in[5] = W_msg, d_in[6] = b_msg : dead code in the reference
    const float* W_u1  = (const float*)d_in[7];
    const float* b_u1  = (const float*)d_in[8];
    const float* W_u2  = (const float*)d_in[9];
    const float* b_u2  = (const float*)d_in[10];
    const float* gamma = (const float*)d_in[11];
    const float* beta  = (const float*)d_in[12];
    float* out = (float*)d_out;

    float* h_ptr = nullptr;
    cudaGetSymbolAddress((void**)&h_ptr, g_h);
    float* w1t_ptr = nullptr;
    cudaGetSymbolAddress((void**)&w1t_ptr, g_W1t);
    float* w2t_ptr = nullptr;
    cudaGetSymbolAddress((void**)&w2t_ptr, g_W2t);

    dim3 tb(32, 8);
    transpose_kernel<<<dim3(4, 8), tb>>>(W_u1, w1t_ptr, 256, 128);
    transpose_kernel<<<dim3(4, 4), tb>>>(W_u2, w2t_ptr, 128, 128);
    build_edges_kernel<<<NN / 8, 256>>>(adj, dist);
    in_proj_kernel<<<NN / 8, 128>>>(x, W_in, b_in);
    for (int s = 0; s < 3; s++) {
        msg_kernel<<<NN, 128>>>();
        update_kernel<<<NN / 4, 128>>>(b_u1, b_u2, gamma, beta,
                                       (s == 2) ? out : h_ptr);
    }
}

// round 8
// speedup vs baseline: 1.6874x; 1.6874x over previous
#include <cuda_runtime.h>

#define NN   4096
#define HH   128
#define CAP  192   // max degree capacity; Binomial(4096,0.02) max ~= 127

// Scratch (device globals: allocation-free per harness rules)
__device__ float4 g_edge[NN * CAP];   // (j_bits, decay, wc, pad) per edge
__device__ int    g_deg[NN];
__device__ float  g_h[NN * HH];
__device__ float  g_m[NN * HH];

// ---- packed fp32x2 helpers (Blackwell FFMA2) ----
__device__ __forceinline__ unsigned long long fma2(
    unsigned long long a, unsigned long long b, unsigned long long c)
{
    unsigned long long d;
    asm("fma.rn.f32x2 %0, %1, %2, %3;" : "=l"(d) : "l"(a), "l"(b), "l"(c));
    return d;
}
__device__ __forceinline__ unsigned long long packdup(float w)
{
    unsigned long long d;
    asm("mov.b64 %0, {%1, %1};" : "=l"(d) : "f"(w));
    return d;
}
__device__ __forceinline__ void unpack2(unsigned long long v, float& lo, float& hi)
{
    asm("mov.b64 {%0, %1}, %2;" : "=f"(lo), "=f"(hi) : "l"(v));
}

// ---------------------------------------------------------------------------
// Build per-row edge list from adj (2% dense) with loop-invariant weights.
// One warp per row; float4 adj scan. Edge order within a row is a fixed
// permutation (summation order is irrelevant and deterministic).
// ---------------------------------------------------------------------------
__global__ __launch_bounds__(256) void build_edges_kernel(
    const float* __restrict__ adj, const float* __restrict__ dist)
{
    int row  = blockIdx.x * 8 + (threadIdx.x >> 5);
    int lane = threadIdx.x & 31;
    if (row >= NN) return;
    const float4* arowv = (const float4*)(adj + (long)row * NN);  // 1024 float4
    const float*  drow  = dist + (long)row * NN;
    unsigned lt = (1u << lane) - 1u;
    int base = 0;
    for (int it = 0; it < 1024; it += 64) {
        float4 a = arowv[it + lane];
        float4 b = arowv[it + 32 + lane];
        unsigned m0 = __ballot_sync(0xffffffffu, a.x != 0.0f);
        unsigned m1 = __ballot_sync(0xffffffffu, a.y != 0.0f);
        unsigned m2 = __ballot_sync(0xffffffffu, a.z != 0.0f);
        unsigned m3 = __ballot_sync(0xffffffffu, a.w != 0.0f);
        unsigned n0 = __ballot_sync(0xffffffffu, b.x != 0.0f);
        unsigned n1 = __ballot_sync(0xffffffffu, b.y != 0.0f);
        unsigned n2 = __ballot_sync(0xffffffffu, b.z != 0.0f);
        unsigned n3 = __ballot_sync(0xffffffffu, b.w != 0.0f);
#pragma unroll
        for (int q = 0; q < 8; q++) {
            unsigned mask;
            float av;
            int col;
            switch (q) {
                case 0: mask = m0; av = a.x; col = (it + lane) * 4 + 0; break;
                case 1: mask = m1; av = a.y; col = (it + lane) * 4 + 1; break;
                case 2: mask = m2; av = a.z; col = (it + lane) * 4 + 2; break;
                case 3: mask = m3; av = a.w; col = (it + lane) * 4 + 3; break;
                case 4: mask = n0; av = b.x; col = (it + 32 + lane) * 4 + 0; break;
                case 5: mask = n1; av = b.y; col = (it + 32 + lane) * 4 + 1; break;
                case 6: mask = n2; av = b.z; col = (it + 32 + lane) * 4 + 2; break;
                default: mask = n3; av = b.w; col = (it + 32 + lane) * 4 + 3; break;
            }
            if (av != 0.0f) {
                int pos = base + __popc(mask & lt);
                if (pos < CAP) {
                    float d     = drow[col];
                    float decay = __expf(d * (-1.0f / 3.0f));
                    float r     = fmaxf(d, 1e-6f);
                    float inv   = 3.5f / r;
                    float i2    = inv * inv;
                    float i6    = i2 * i2 * i2;
                    float wc    = 0.04f * (i6 * i6 - i6);
                    g_edge[row * CAP + pos] =
                        make_float4(__int_as_float(col), decay, wc, 0.0f);
                }
            }
            base += __popc(mask);
        }
    }
    if (lane == 0) g_deg[row] = (base < CAP) ? base : CAP;
}

// ---------------------------------------------------------------------------
// h = x @ W_in + b_in  (4096x64 @ 64x128); 4 rows/block, grid 1024.
// Transposed smem activations + row-packed f32x2, coalesced scalar W loads.
// ---------------------------------------------------------------------------
__global__ __launch_bounds__(128) void in_proj_kernel(
    const float* __restrict__ x, const float* __restrict__ W,
    const float* __restrict__ b)
{
    __shared__ __align__(16) float s_xT[64 * 4];   // [k][r]
    int c  = threadIdx.x;
    int r0 = blockIdx.x * 4;
    for (int i = threadIdx.x; i < 4 * 64; i += 128) {
        int r = i >> 6, k = i & 63;
        s_xT[k * 4 + r] = x[(long)(r0 + r) * 64 + k];
    }
    __syncthreads();

    typedef unsigned long long u64;
    u64 p01 = 0ull, p23 = 0ull;
    const float* wcol = W + c;
#pragma unroll 8
    for (int k = 0; k < 64; k++) {
        u64 ww = packdup(wcol[k * HH]);
        ulonglong2 av = *(const ulonglong2*)&s_xT[k * 4];
        p01 = fma2(av.x, ww, p01);
        p23 = fma2(av.y, ww, p23);
    }
    float h0, h1, h2, h3;
    unpack2(p01, h0, h1);
    unpack2(p23, h2, h3);
    float bias = b[c];
    g_h[(long)(r0 + 0) * HH + c] = h0 + bias;
    g_h[(long)(r0 + 1) * HH + c] = h1 + bias;
    g_h[(long)(r0 + 2) * HH + c] = h2 + bias;
    g_h[(long)(r0 + 3) * HH + c] = h3 + bias;
}

// ---------------------------------------------------------------------------
// m_i = sum_{j in N(i)} (decay_ij * relu(<h_i, h_j>) + wc_ij) * h_j
// One block (4 warps) per row; each warp processes 4 edges per iteration so
// four shfl-reduce chains interleave (exposed chain latency /2 vs pairs).
// ---------------------------------------------------------------------------
__global__ __launch_bounds__(128) void msg_kernel()
{
    __shared__ float s_hi[HH];
    __shared__ float s_m[4 * HH];
    int row  = blockIdx.x;
    int tid  = threadIdx.x;
    int wid  = tid >> 5;
    int lane = tid & 31;

    s_hi[tid] = g_h[(long)row * HH + tid];
    __syncthreads();
    float4 hi4 = *(const float4*)&s_hi[lane * 4];

    int deg = g_deg[row];
    const float4* ebase = &g_edge[row * CAP];
    float4 acc = make_float4(0.f, 0.f, 0.f, 0.f);

    for (int e0 = wid * 4; e0 < deg; e0 += 16) {
        float4 em[4], hj[4];
#pragma unroll
        for (int q = 0; q < 4; q++) {
            bool v = (e0 + q) < deg;
            em[q] = v ? ebase[e0 + q] : make_float4(0.f, 0.f, 0.f, 0.f);
            int j = v ? __float_as_int(em[q].x) : 0;
            hj[q] = *(const float4*)&g_h[(long)j * HH + lane * 4];
        }
        float d[4];
#pragma unroll
        for (int q = 0; q < 4; q++)
            d[q] = hi4.x * hj[q].x + hi4.y * hj[q].y
                 + hi4.z * hj[q].z + hi4.w * hj[q].w;
#pragma unroll
        for (int o = 16; o > 0; o >>= 1) {
#pragma unroll
            for (int q = 0; q < 4; q++)
                d[q] += __shfl_xor_sync(0xffffffffu, d[q], o);
        }
#pragma unroll
        for (int q = 0; q < 4; q++) {
            float cf = fmaf(em[q].y, fmaxf(d[q], 0.0f), em[q].z);  // 0 if invalid
            acc.x = fmaf(cf, hj[q].x, acc.x);
            acc.y = fmaf(cf, hj[q].y, acc.y);
            acc.z = fmaf(cf, hj[q].z, acc.z);
            acc.w = fmaf(cf, hj[q].w, acc.w);
        }
    }
    *(float4*)&s_m[wid * HH + lane * 4] = acc;
    __syncthreads();
    g_m[(long)row * HH + tid] =
        s_m[tid] + s_m[HH + tid] + s_m[2 * HH + tid] + s_m[3 * HH + tid];
}

// ---------------------------------------------------------------------------
// Fused update: t = relu([h|m]@W1+b1); delta = t@W2+b2; out = LN(h+delta)
// 4 rows/block, grid 1024. Transposed smem activations (broadcast LDS.128,
// rows packed as f32x2 pairs) + coalesced scalar weight LDG + FFMA2.
// ---------------------------------------------------------------------------
__global__ __launch_bounds__(128) void update_kernel(
    const float* __restrict__ W1, const float* __restrict__ b1,
    const float* __restrict__ W2, const float* __restrict__ b2,
    const float* __restrict__ gamma, const float* __restrict__ beta,
    float* __restrict__ out)
{
    __shared__ __align__(16) float s_catT[256 * 4];  // [k][r]: k<128 h, k>=128 m
    __shared__ __align__(16) float s_tT[128 * 4];    // [k][r]
    __shared__ float s_y[4][132];
    int c  = threadIdx.x;
    int r0 = blockIdx.x * 4;

    for (int i = threadIdx.x; i < 4 * 128; i += 128) {
        int r = i >> 7, k = i & 127;
        s_catT[k * 4 + r]         = g_h[(long)(r0 + r) * HH + k];
        s_catT[(128 + k) * 4 + r] = g_m[(long)(r0 + r) * HH + k];
    }
    __syncthreads();

    typedef unsigned long long u64;
    // ---- mlp1: t[r][c] = relu(sum_k cat[r][k]*W1[k][c] + b1[c]) ----
    u64 p01 = 0ull, p23 = 0ull;
    const float* w1col = W1 + c;
#pragma unroll 8
    for (int k = 0; k < 256; k++) {
        u64 ww = packdup(w1col[k * HH]);
        ulonglong2 av = *(const ulonglong2*)&s_catT[k * 4];
        p01 = fma2(av.x, ww, p01);
        p23 = fma2(av.y, ww, p23);
    }
    {
        float t0, t1, t2, t3;
        unpack2(p01, t0, t1);
        unpack2(p23, t2, t3);
        float bias = b1[c];
        *(float4*)&s_tT[c * 4] = make_float4(
            fmaxf(t0 + bias, 0.0f), fmaxf(t1 + bias, 0.0f),
            fmaxf(t2 + bias, 0.0f), fmaxf(t3 + bias, 0.0f));
    }
    __syncthreads();

    // ---- mlp2: delta[r][c] = sum_k t[r][k]*W2[k][c] + b2[c] ----
    p01 = 0ull; p23 = 0ull;
    const float* w2col = W2 + c;
#pragma unroll 8
    for (int k = 0; k < 128; k++) {
        u64 ww = packdup(w2col[k * HH]);
        ulonglong2 tv = *(const ulonglong2*)&s_tT[k * 4];
        p01 = fma2(tv.x, ww, p01);
        p23 = fma2(tv.y, ww, p23);
    }
    {
        float d0, d1, d2, d3;
        unpack2(p01, d0, d1);
        unpack2(p23, d2, d3);
        float bias = b2[c];
        float4 hv = *(const float4*)&s_catT[c * 4];   // h rows 0..3 at k=c
        s_y[0][c] = hv.x + d0 + bias;
        s_y[1][c] = hv.y + d1 + bias;
        s_y[2][c] = hv.z + d2 + bias;
        s_y[3][c] = hv.w + d3 + bias;
    }
    __syncthreads();

    // ---- layernorm: warp wid handles row wid; lane owns 4 cols ----
    int wid  = c >> 5;
    int lane = c & 31;
    float4 gm = *(const float4*)&gamma[lane * 4];
    float4 bt = *(const float4*)&beta[lane * 4];
    {
        float4 yv = *(const float4*)&s_y[wid][lane * 4];
        float s = yv.x + yv.y + yv.z + yv.w;
#pragma unroll
        for (int o = 16; o > 0; o >>= 1)
            s += __shfl_xor_sync(0xffffffffu, s, o);
        float mu = s * (1.0f / 128.0f);
        float dx = yv.x - mu, dy = yv.y - mu, dz = yv.z - mu, dw = yv.w - mu;
        float sq = dx * dx + dy * dy + dz * dz + dw * dw;
#pragma unroll
        for (int o = 16; o > 0; o >>= 1)
            sq += __shfl_xor_sync(0xffffffffu, sq, o);
        float rs = rsqrtf(sq * (1.0f / 128.0f) + 1e-5f);
        float4 o4;
        o4.x = dx * rs * gm.x + bt.x;
        o4.y = dy * rs * gm.y + bt.y;
        o4.z = dz * rs * gm.z + bt.z;
        o4.w = dw * rs * gm.w + bt.w;
        *(float4*)&out[(long)(r0 + wid) * HH + lane * 4] = o4;
    }
}

// ---------------------------------------------------------------------------
extern "C" void kernel_launch(void* const* d_in, const int* in_sizes, int n_in,
                              void* d_out, int out_size)
{
    const float* x     = (const float*)d_in[0];
    const float* adj   = (const float*)d_in[1];
    const float* dist  = (const float*)d_in[2];
    const float* W_in  = (const float*)d_in[3];
    const float* b_in  = (const float*)d_in[4];
    // d_in[5] = W_msg, d_in[6] = b_msg : dead code in the reference
    const float* W_u1  = (const float*)d_in[7];
    const float* b_u1  = (const float*)d_in[8];
    const float* W_u2  = (const float*)d_in[9];
    const float* b_u2  = (const float*)d_in[10];
    const float* gamma = (const float*)d_in[11];
    const float* beta  = (const float*)d_in[12];
    float* out = (float*)d_out;

    float* h_ptr = nullptr;
    cudaGetSymbolAddress((void**)&h_ptr, g_h);

    build_edges_kernel<<<NN / 8, 256>>>(adj, dist);
    in_proj_kernel<<<NN / 4, 128>>>(x, W_in, b_in);
    for (int s = 0; s < 3; s++) {
        msg_kernel<<<NN, 128>>>();
        update_kernel<<<NN / 4, 128>>>(W_u1, b_u1, W_u2, b_u2, gamma, beta,
                                       (s == 2) ? out : h_ptr);
    }
}

// round 10
// speedup vs baseline: 1.7098x; 1.0133x over previous
#include <cuda_runtime.h>

#define NN   4096
#define HH   128
#define CAP  192   // max degree capacity; Binomial(4096,0.02) max ~= 127

// Scratch (device globals: allocation-free per harness rules)
__device__ float4 g_edge[NN * CAP];   // (j_bits, decay, wc, pad) per edge
__device__ int    g_deg[NN];
__device__ float  g_h[NN * HH];
__device__ float  g_m[NN * HH];

// ---- packed fp32x2 helpers (Blackwell FFMA2 / FADD2) ----
__device__ __forceinline__ unsigned long long fma2(
    unsigned long long a, unsigned long long b, unsigned long long c)
{
    unsigned long long d;
    asm("fma.rn.f32x2 %0, %1, %2, %3;" : "=l"(d) : "l"(a), "l"(b), "l"(c));
    return d;
}
__device__ __forceinline__ unsigned long long fadd2(
    unsigned long long a, unsigned long long b)
{
    unsigned long long d;
    asm("add.rn.f32x2 %0, %1, %2;" : "=l"(d) : "l"(a), "l"(b));
    return d;
}
__device__ __forceinline__ unsigned long long packdup(float w)
{
    unsigned long long d;
    asm("mov.b64 %0, {%1, %1};" : "=l"(d) : "f"(w));
    return d;
}
__device__ __forceinline__ void unpack2(unsigned long long v, float& lo, float& hi)
{
    asm("mov.b64 {%0, %1}, %2;" : "=f"(lo), "=f"(hi) : "l"(v));
}

// ---------------------------------------------------------------------------
// Build per-row edge list from adj (2% dense) with loop-invariant weights.
// One warp per row; float4 adj scan. Edge order within a row is a fixed
// permutation (summation order is irrelevant and deterministic).
// ---------------------------------------------------------------------------
__global__ __launch_bounds__(256) void build_edges_kernel(
    const float* __restrict__ adj, const float* __restrict__ dist)
{
    int row  = blockIdx.x * 8 + (threadIdx.x >> 5);
    int lane = threadIdx.x & 31;
    if (row >= NN) return;
    const float4* arowv = (const float4*)(adj + (long)row * NN);  // 1024 float4
    const float*  drow  = dist + (long)row * NN;
    unsigned lt = (1u << lane) - 1u;
    int base = 0;
    for (int it = 0; it < 1024; it += 64) {
        float4 a = arowv[it + lane];
        float4 b = arowv[it + 32 + lane];
        unsigned m0 = __ballot_sync(0xffffffffu, a.x != 0.0f);
        unsigned m1 = __ballot_sync(0xffffffffu, a.y != 0.0f);
        unsigned m2 = __ballot_sync(0xffffffffu, a.z != 0.0f);
        unsigned m3 = __ballot_sync(0xffffffffu, a.w != 0.0f);
        unsigned n0 = __ballot_sync(0xffffffffu, b.x != 0.0f);
        unsigned n1 = __ballot_sync(0xffffffffu, b.y != 0.0f);
        unsigned n2 = __ballot_sync(0xffffffffu, b.z != 0.0f);
        unsigned n3 = __ballot_sync(0xffffffffu, b.w != 0.0f);
#pragma unroll
        for (int q = 0; q < 8; q++) {
            unsigned mask;
            float av;
            int col;
            switch (q) {
                case 0: mask = m0; av = a.x; col = (it + lane) * 4 + 0; break;
                case 1: mask = m1; av = a.y; col = (it + lane) * 4 + 1; break;
                case 2: mask = m2; av = a.z; col = (it + lane) * 4 + 2; break;
                case 3: mask = m3; av = a.w; col = (it + lane) * 4 + 3; break;
                case 4: mask = n0; av = b.x; col = (it + 32 + lane) * 4 + 0; break;
                case 5: mask = n1; av = b.y; col = (it + 32 + lane) * 4 + 1; break;
                case 6: mask = n2; av = b.z; col = (it + 32 + lane) * 4 + 2; break;
                default: mask = n3; av = b.w; col = (it + 32 + lane) * 4 + 3; break;
            }
            if (av != 0.0f) {
                int pos = base + __popc(mask & lt);
                if (pos < CAP) {
                    float d     = drow[col];
                    float decay = __expf(d * (-1.0f / 3.0f));
                    float r     = fmaxf(d, 1e-6f);
                    float inv   = 3.5f / r;
                    float i2    = inv * inv;
                    float i6    = i2 * i2 * i2;
                    float wc    = 0.04f * (i6 * i6 - i6);
                    g_edge[row * CAP + pos] =
                        make_float4(__int_as_float(col), decay, wc, 0.0f);
                }
            }
            base += __popc(mask);
        }
    }
    if (lane == 0) g_deg[row] = (base < CAP) ? base : CAP;
}

// ---------------------------------------------------------------------------
// h = x @ W_in + b_in  (4096x64 @ 64x128); 4 rows/block, grid 1024.
// Transposed smem activations + row-packed f32x2, coalesced scalar W loads.
// ---------------------------------------------------------------------------
__global__ __launch_bounds__(128) void in_proj_kernel(
    const float* __restrict__ x, const float* __restrict__ W,
    const float* __restrict__ b)
{
    __shared__ __align__(16) float s_xT[64 * 4];   // [k][r]
    int c  = threadIdx.x;
    int r0 = blockIdx.x * 4;
    for (int i = threadIdx.x; i < 4 * 64; i += 128) {
        int r = i >> 6, k = i & 63;
        s_xT[k * 4 + r] = x[(long)(r0 + r) * 64 + k];
    }
    __syncthreads();

    typedef unsigned long long u64;
    u64 p01 = 0ull, p23 = 0ull;
    const float* wcol = W + c;
#pragma unroll 8
    for (int k = 0; k < 64; k++) {
        u64 ww = packdup(wcol[k * HH]);
        ulonglong2 av = *(const ulonglong2*)&s_xT[k * 4];
        p01 = fma2(av.x, ww, p01);
        p23 = fma2(av.y, ww, p23);
    }
    float h0, h1, h2, h3;
    unpack2(p01, h0, h1);
    unpack2(p23, h2, h3);
    float bias = b[c];
    g_h[(long)(r0 + 0) * HH + c] = h0 + bias;
    g_h[(long)(r0 + 1) * HH + c] = h1 + bias;
    g_h[(long)(r0 + 2) * HH + c] = h2 + bias;
    g_h[(long)(r0 + 3) * HH + c] = h3 + bias;
}

// ---------------------------------------------------------------------------
// m_i = sum_{j in N(i)} (decay_ij * relu(<h_i, h_j>) + wc_ij) * h_j
// One block (4 warps) per row; each warp processes 4 edges per iteration so
// four shfl-reduce chains interleave.
// ---------------------------------------------------------------------------
__global__ __launch_bounds__(128) void msg_kernel()
{
    __shared__ float s_hi[HH];
    __shared__ float s_m[4 * HH];
    int row  = blockIdx.x;
    int tid  = threadIdx.x;
    int wid  = tid >> 5;
    int lane = tid & 31;

    s_hi[tid] = g_h[(long)row * HH + tid];
    __syncthreads();
    float4 hi4 = *(const float4*)&s_hi[lane * 4];

    int deg = g_deg[row];
    const float4* ebase = &g_edge[row * CAP];
    float4 acc = make_float4(0.f, 0.f, 0.f, 0.f);

    for (int e0 = wid * 4; e0 < deg; e0 += 16) {
        float4 em[4], hj[4];
#pragma unroll
        for (int q = 0; q < 4; q++) {
            bool v = (e0 + q) < deg;
            em[q] = v ? ebase[e0 + q] : make_float4(0.f, 0.f, 0.f, 0.f);
            int j = v ? __float_as_int(em[q].x) : 0;
            hj[q] = *(const float4*)&g_h[(long)j * HH + lane * 4];
        }
        float d[4];
#pragma unroll
        for (int q = 0; q < 4; q++)
            d[q] = hi4.x * hj[q].x + hi4.y * hj[q].y
                 + hi4.z * hj[q].z + hi4.w * hj[q].w;
#pragma unroll
        for (int o = 16; o > 0; o >>= 1) {
#pragma unroll
            for (int q = 0; q < 4; q++)
                d[q] += __shfl_xor_sync(0xffffffffu, d[q], o);
        }
#pragma unroll
        for (int q = 0; q < 4; q++) {
            float cf = fmaf(em[q].y, fmaxf(d[q], 0.0f), em[q].z);  // 0 if invalid
            acc.x = fmaf(cf, hj[q].x, acc.x);
            acc.y = fmaf(cf, hj[q].y, acc.y);
            acc.z = fmaf(cf, hj[q].z, acc.z);
            acc.w = fmaf(cf, hj[q].w, acc.w);
        }
    }
    *(float4*)&s_m[wid * HH + lane * 4] = acc;
    __syncthreads();
    g_m[(long)row * HH + tid] =
        s_m[tid] + s_m[HH + tid] + s_m[2 * HH + tid] + s_m[3 * HH + tid];
}

// ---------------------------------------------------------------------------
// Fused update: t = relu([h|m]@W1+b1); delta = t@W2+b2; out = LN(h+delta)
// 8 rows/block, 256 threads, grid 512 (27.7 warps/SM).
// Thread = (c = tid&127, half = tid>>7). Each half covers half the k-range;
// partial sums combined in smem with packed f32x2 adds. Each weight scalar
// now feeds 8 rows -> weight-LDG instruction count per SM halves vs R8.
// ---------------------------------------------------------------------------
__global__ __launch_bounds__(256) void update_kernel(
    const float* __restrict__ W1, const float* __restrict__ b1,
    const float* __restrict__ W2, const float* __restrict__ b2,
    const float* __restrict__ gamma, const float* __restrict__ beta,
    float* __restrict__ out)
{
    typedef unsigned long long u64;
    __shared__ __align__(16) float s_catT[256 * 8];   // [k][r]: k<128 h, k>=128 m (8KB)
    __shared__ __align__(16) float s_tT[128 * 8];     // [k][r] (4KB)
    __shared__ __align__(16) u64   s_part[128 * 4];   // half-1 partials (4KB)
    __shared__ float s_y[8][132];
    int tid  = threadIdx.x;
    int c    = tid & 127;
    int half = tid >> 7;
    int r0   = blockIdx.x * 8;

    for (int i = tid; i < 8 * 128; i += 256) {
        int r = i >> 7, k = i & 127;
        s_catT[k * 8 + r]         = g_h[(long)(r0 + r) * HH + k];
        s_catT[(128 + k) * 8 + r] = g_m[(long)(r0 + r) * HH + k];
    }
    __syncthreads();

    // ---- mlp1: t[r][c] = relu(sum_k cat[r][k]*W1[k][c] + b1[c]) ----
    u64 p0 = 0ull, p1 = 0ull, p2 = 0ull, p3 = 0ull;
    {
        const float* w1col = W1 + (half * 128) * HH + c;
        const float* base  = &s_catT[(half * 128) * 8];
#pragma unroll 8
        for (int k = 0; k < 128; k++) {
            u64 ww = packdup(w1col[k * HH]);
            ulonglong2 a01 = *(const ulonglong2*)(base + k * 8);
            ulonglong2 a23 = *(const ulonglong2*)(base + k * 8 + 4);
            p0 = fma2(a01.x, ww, p0);
            p1 = fma2(a01.y, ww, p1);
            p2 = fma2(a23.x, ww, p2);
            p3 = fma2(a23.y, ww, p3);
        }
    }
    if (half == 1) {
        *(ulonglong2*)&s_part[c * 4]     = make_ulonglong2(p0, p1);
        *(ulonglong2*)&s_part[c * 4 + 2] = make_ulonglong2(p2, p3);
    }
    __syncthreads();
    if (half == 0) {
        ulonglong2 q01 = *(const ulonglong2*)&s_part[c * 4];
        ulonglong2 q23 = *(const ulonglong2*)&s_part[c * 4 + 2];
        p0 = fadd2(p0, q01.x); p1 = fadd2(p1, q01.y);
        p2 = fadd2(p2, q23.x); p3 = fadd2(p3, q23.y);
        float t0, t1, t2, t3, t4, t5, t6, t7;
        unpack2(p0, t0, t1); unpack2(p1, t2, t3);
        unpack2(p2, t4, t5); unpack2(p3, t6, t7);
        float bias = b1[c];
        *(float4*)&s_tT[c * 8]     = make_float4(
            fmaxf(t0 + bias, 0.0f), fmaxf(t1 + bias, 0.0f),
            fmaxf(t2 + bias, 0.0f), fmaxf(t3 + bias, 0.0f));
        *(float4*)&s_tT[c * 8 + 4] = make_float4(
            fmaxf(t4 + bias, 0.0f), fmaxf(t5 + bias, 0.0f),
            fmaxf(t6 + bias, 0.0f), fmaxf(t7 + bias, 0.0f));
    }
    __syncthreads();

    // ---- mlp2: delta[r][c] = sum_k t[r][k]*W2[k][c] + b2[c] ----
    p0 = 0ull; p1 = 0ull; p2 = 0ull; p3 = 0ull;
    {
        const float* w2col = W2 + (half * 64) * HH + c;
        const float* base  = &s_tT[(half * 64) * 8];
#pragma unroll 8
        for (int k = 0; k < 64; k++) {
            u64 ww = packdup(w2col[k * HH]);
            ulonglong2 a01 = *(const ulonglong2*)(base + k * 8);
            ulonglong2 a23 = *(const ulonglong2*)(base + k * 8 + 4);
            p0 = fma2(a01.x, ww, p0);
            p1 = fma2(a01.y, ww, p1);
            p2 = fma2(a23.x, ww, p2);
            p3 = fma2(a23.y, ww, p3);
        }
    }
    if (half == 1) {
        *(ulonglong2*)&s_part[c * 4]     = make_ulonglong2(p0, p1);
        *(ulonglong2*)&s_part[c * 4 + 2] = make_ulonglong2(p2, p3);
    }
    __syncthreads();
    if (half == 0) {
        ulonglong2 q01 = *(const ulonglong2*)&s_part[c * 4];
        ulonglong2 q23 = *(const ulonglong2*)&s_part[c * 4 + 2];
        p0 = fadd2(p0, q01.x); p1 = fadd2(p1, q01.y);
        p2 = fadd2(p2, q23.x); p3 = fadd2(p3, q23.y);
        float d0, d1, d2, d3, d4, d5, d6, d7;
        unpack2(p0, d0, d1); unpack2(p1, d2, d3);
        unpack2(p2, d4, d5); unpack2(p3, d6, d7);
        float bias = b2[c];
        float4 h03 = *(const float4*)&s_catT[c * 8];      // h rows 0..3 at k=c
        float4 h47 = *(const float4*)&s_catT[c * 8 + 4];  // h rows 4..7 at k=c
        s_y[0][c] = h03.x + d0 + bias;
        s_y[1][c] = h03.y + d1 + bias;
        s_y[2][c] = h03.z + d2 + bias;
        s_y[3][c] = h03.w + d3 + bias;
        s_y[4][c] = h47.x + d4 + bias;
        s_y[5][c] = h47.y + d5 + bias;
        s_y[6][c] = h47.z + d6 + bias;
        s_y[7][c] = h47.w + d7 + bias;
    }
    __syncthreads();

    // ---- layernorm: 8 warps, warp wid handles row wid; lane owns 4 cols ----
    int wid  = tid >> 5;
    int lane = tid & 31;
    float4 gm = *(const float4*)&gamma[lane * 4];
    float4 bt = *(const float4*)&beta[lane * 4];
    {
        float4 yv = *(const float4*)&s_y[wid][lane * 4];
        float s = yv.x + yv.y + yv.z + yv.w;
#pragma unroll
        for (int o = 16; o > 0; o >>= 1)
            s += __shfl_xor_sync(0xffffffffu, s, o);
        float mu = s * (1.0f / 128.0f);
        float dx = yv.x - mu, dy = yv.y - mu, dz = yv.z - mu, dw = yv.w - mu;
        float sq = dx * dx + dy * dy + dz * dz + dw * dw;
#pragma unroll
        for (int o = 16; o > 0; o >>= 1)
            sq += __shfl_xor_sync(0xffffffffu, sq, o);
        float rs = rsqrtf(sq * (1.0f / 128.0f) + 1e-5f);
        float4 o4;
        o4.x = dx * rs * gm.x + bt.x;
        o4.y = dy * rs * gm.y + bt.y;
        o4.z = dz * rs * gm.z + bt.z;
        o4.w = dw * rs * gm.w + bt.w;
        *(float4*)&out[(long)(r0 + wid) * HH + lane * 4] = o4;
    }
}

// ---------------------------------------------------------------------------
extern "C" void kernel_launch(void* const* d_in, const int* in_sizes, int n_in,
                              void* d_out, int out_size)
{
    const float* x     = (const float*)d_in[0];
    const float* adj   = (const float*)d_in[1];
    const float* dist  = (const float*)d_in[2];
    const float* W_in  = (const float*)d_in[3];
    const float* b_in  = (const float*)d_in[4];
    // d_in[5] = W_msg, d_in[6] = b_msg : dead code in the reference
    const float* W_u1  = (const float*)d_in[7];
    const float* b_u1  = (const float*)d_in[8];
    const float* W_u2  = (const float*)d_in[9];
    const float* b_u2  = (const float*)d_in[10];
    const float* gamma = (const float*)d_in[11];
    const float* beta  = (const float*)d_in[12];
    float* out = (float*)d_out;

    float* h_ptr = nullptr;
    cudaGetSymbolAddress((void**)&h_ptr, g_h);

    build_edges_kernel<<<NN / 8, 256>>>(adj, dist);
    in_proj_kernel<<<NN / 4, 128>>>(x, W_in, b_in);
    for (int s = 0; s < 3; s++) {
        msg_kernel<<<NN, 128>>>();
        update_kernel<<<NN / 8, 256>>>(W_u1, b_u1, W_u2, b_u2, gamma, beta,
                                       (s == 2) ? out : h_ptr);
    }
}